// round 10
// baseline (speedup 1.0000x reference)
#include <cuda_runtime.h>

// LSTM autoencoder, fully fused. B=4096, T=512, F=8, H=16.
// R5: break the volatile-asm scheduling fence.
//  - x input projection software-pipelined one step ahead (ping-pong reg sets)
//  - global loads non-volatile (ptxas free to hoist/interleave)
//  - recurrent accumulation split into two half-chains (+add2 combine)
// Two batch elements per thread (weights register-shared), half-warp = element.

#define B_ 4096
#define T_ 512
#define F_ 8
#define H_ 16
#define XOFF (T_ * F_)

typedef unsigned long long u64;

__device__ __forceinline__ u64 pk2(float lo, float hi) {
    u64 r; asm("mov.b64 %0,{%1,%2};" : "=l"(r) : "f"(lo), "f"(hi)); return r;
}
__device__ __forceinline__ void fma2(u64& d, u64 a, u64 b) {
    asm("fma.rn.f32x2 %0,%1,%2,%0;" : "+l"(d) : "l"(a), "l"(b));
}
__device__ __forceinline__ void mul2(u64& d, u64 a, u64 b) {
    asm("mul.rn.f32x2 %0,%1,%2;" : "=l"(d) : "l"(a), "l"(b));
}
__device__ __forceinline__ void add2(u64& d, u64 a, u64 b) {
    asm("add.rn.f32x2 %0,%1,%2;" : "=l"(d) : "l"(a), "l"(b));
}
__device__ __forceinline__ float hadd2(u64 v) {
    float lo, hi; asm("mov.b64 {%0,%1},%2;" : "=f"(lo), "=f"(hi) : "l"(v));
    return lo + hi;
}
__device__ __forceinline__ float tanh_fast(float x) {
    float r; asm("tanh.approx.f32 %0,%1;" : "=f"(r) : "f"(x)); return r;
}
__device__ __forceinline__ float sigm(float x) {          // 0.5*tanh(x/2)+0.5
    return __fmaf_rn(0.5f, tanh_fast(0.5f * x), 0.5f);
}
// smem ops stay volatile: they carry the only cross-step ordering requirement
__device__ __forceinline__ void lds2(u64& a, u64& b, unsigned addr) {
    asm volatile("ld.shared.v2.u64 {%0,%1},[%2];" : "=l"(a), "=l"(b) : "r"(addr));
}
__device__ __forceinline__ void sts1(unsigned addr, float v) {
    asm volatile("st.shared.b32 [%0],%1;" :: "r"(addr), "f"(v));
}
// global loads NON-volatile: scheduler may hoist them arbitrarily
__device__ __forceinline__ void ldg2(u64& a, u64& b, const float* p) {
    asm("ld.global.nc.v2.u64 {%0,%1},[%2];" : "=l"(a), "=l"(b) : "l"(p));
}
__device__ __forceinline__ void prefetch_l1(const float* p) {
    float d; asm volatile("ld.global.nc.b32 %0,[%1];" : "=f"(d) : "l"(p));
}
#define CBAR() asm volatile("" ::: "memory")

// ---------------- encoder step ----------------
// xp: this step's gate accumulators (bias + Wih*x_t, prepared last step)
// nx: next step's accumulators, produced here (ping-pong with xp)
__device__ __forceinline__ void estep(
    int t, unsigned ra, unsigned wa, const float* xr,
    u64 (&xp)[8], u64 (&nx)[8],
    const u64 (&wh)[4][8], const u64 (&wi)[4][4], const float (&bias)[4],
    float& h0, float& c0, float& h1, float& c1, int u, bool pf)
{
    u64 p[8], q[8];
    lds2(p[0],p[1], ra);      lds2(p[2],p[3], ra + 16);
    lds2(p[4],p[5], ra + 32); lds2(p[6],p[7], ra + 48);
    lds2(q[0],q[1], ra + 96); lds2(q[2],q[3], ra + 112);
    lds2(q[4],q[5], ra + 128);lds2(q[6],q[7], ra + 144);

    if (pf) {
        int tp = (t + 6 < T_) ? (t + 6) : (T_ - 1);
        prefetch_l1(xr + tp * F_);
        prefetch_l1(xr + XOFF + tp * F_);
    }

    // ---- next-step input projection (independent of this step's chain) ----
    int tn = (t + 1 < T_) ? (t + 1) : (T_ - 1);
    const float* xt = xr + tn * F_;
    u64 xv[4], yv[4];
    ldg2(xv[0], xv[1], xt);         ldg2(xv[2], xv[3], xt + 4);
    ldg2(yv[0], yv[1], xt + XOFF);  ldg2(yv[2], yv[3], xt + XOFF + 4);
    #pragma unroll
    for (int g = 0; g < 4; ++g) {
        nx[g]     = pk2(bias[g], 0.f);
        nx[4 + g] = pk2(bias[g], 0.f);
    }
    #pragma unroll
    for (int j = 0; j < 4; ++j)
        #pragma unroll
        for (int g = 0; g < 4; ++g) {
            fma2(nx[g],     xv[j], wi[g][j]);
            fma2(nx[4 + g], yv[j], wi[g][j]);
        }

    // ---- recurrent projection, split into two half-chains ----
    u64 s[8];
    #pragma unroll
    for (int g = 0; g < 4; ++g) {
        mul2(s[g],     p[4], wh[g][4]);
        mul2(s[4 + g], q[4], wh[g][4]);
    }
    #pragma unroll
    for (int j = 0; j < 4; ++j)
        #pragma unroll
        for (int g = 0; g < 4; ++g) {
            fma2(xp[g],     p[j], wh[g][j]);
            fma2(xp[4 + g], q[j], wh[g][j]);
        }
    #pragma unroll
    for (int j = 5; j < 8; ++j)
        #pragma unroll
        for (int g = 0; g < 4; ++g) {
            fma2(s[g],     p[j], wh[g][j]);
            fma2(s[4 + g], q[j], wh[g][j]);
        }
    #pragma unroll
    for (int g = 0; g < 8; ++g) add2(xp[g], xp[g], s[g]);

    // ---- activations & state update ----
    float ig0 = sigm(hadd2(xp[0])),      fg0 = sigm(hadd2(xp[1]));
    float gg0 = tanh_fast(hadd2(xp[2])), og0 = sigm(hadd2(xp[3]));
    float ig1 = sigm(hadd2(xp[4])),      fg1 = sigm(hadd2(xp[5]));
    float gg1 = tanh_fast(hadd2(xp[6])), og1 = sigm(hadd2(xp[7]));
    c0 = __fmaf_rn(fg0, c0, ig0 * gg0);
    c1 = __fmaf_rn(fg1, c1, ig1 * gg1);
    h0 = og0 * tanh_fast(c0);
    h1 = og1 * tanh_fast(c1);
    sts1(wa + u * 4, h0);
    sts1(wa + 96 + u * 4, h1);
}

// ---------------- decoder step ----------------
__device__ __forceinline__ void dstep(
    int t, unsigned ra, unsigned wa,
    const u64 (&xg)[8], const u64 (&wh)[4][8], const u64 (&ow)[8], float obv,
    float& h0, float& c0, float& h1, float& c1,
    float* outp0, float* outp1, int u)
{
    u64 p[8], q[8];
    lds2(p[0],p[1], ra);      lds2(p[2],p[3], ra + 16);
    lds2(p[4],p[5], ra + 32); lds2(p[6],p[7], ra + 48);
    lds2(q[0],q[1], ra + 96); lds2(q[2],q[3], ra + 112);
    lds2(q[4],q[5], ra + 128);lds2(q[6],q[7], ra + 144);

    u64 s1[8], s2[8], oa, oc;
    #pragma unroll
    for (int g = 0; g < 4; ++g) {
        mul2(s1[g],     p[0], wh[g][0]);  mul2(s1[4 + g], q[0], wh[g][0]);
        mul2(s2[g],     p[4], wh[g][4]);  mul2(s2[4 + g], q[4], wh[g][4]);
    }
    mul2(oa, p[0], ow[0]);  mul2(oc, q[0], ow[0]);
    fma2(oa, p[4], ow[4]);  fma2(oc, q[4], ow[4]);
    #pragma unroll
    for (int j = 1; j < 4; ++j) {
        #pragma unroll
        for (int g = 0; g < 4; ++g) {
            fma2(s1[g],     p[j], wh[g][j]);
            fma2(s1[4 + g], q[j], wh[g][j]);
        }
        fma2(oa, p[j], ow[j]);  fma2(oc, q[j], ow[j]);
    }
    #pragma unroll
    for (int j = 5; j < 8; ++j) {
        #pragma unroll
        for (int g = 0; g < 4; ++g) {
            fma2(s2[g],     p[j], wh[g][j]);
            fma2(s2[4 + g], q[j], wh[g][j]);
        }
        fma2(oa, p[j], ow[j]);  fma2(oc, q[j], ow[j]);
    }

    u64 a[8];
    #pragma unroll
    for (int g = 0; g < 8; ++g) {
        add2(a[g], s1[g], s2[g]);
        add2(a[g], a[g], xg[g]);
    }

    if (t > 0 && u < 8) {
        outp0[(t - 1) * F_ + u] = hadd2(oa) + obv;   // decoded[t-1] @ oW^T
        outp1[(t - 1) * F_ + u] = hadd2(oc) + obv;
    }

    float ig0 = sigm(hadd2(a[0])),      fg0 = sigm(hadd2(a[1]));
    float gg0 = tanh_fast(hadd2(a[2])), og0 = sigm(hadd2(a[3]));
    float ig1 = sigm(hadd2(a[4])),      fg1 = sigm(hadd2(a[5]));
    float gg1 = tanh_fast(hadd2(a[6])), og1 = sigm(hadd2(a[7]));
    c0 = __fmaf_rn(fg0, c0, ig0 * gg0);
    c1 = __fmaf_rn(fg1, c1, ig1 * gg1);
    h0 = og0 * tanh_fast(c0);
    h1 = og1 * tanh_fast(c1);
    sts1(wa + u * 4, h0);
    sts1(wa + 96 + u * 4, h1);
}

__global__ __launch_bounds__(128, 2)
void lstm_ae_kernel(const float* __restrict__ x,
                    const float* __restrict__ eWih, const float* __restrict__ eWhh,
                    const float* __restrict__ ebih, const float* __restrict__ ebhh,
                    const float* __restrict__ dWih, const float* __restrict__ dWhh,
                    const float* __restrict__ dbih, const float* __restrict__ dbhh,
                    const float* __restrict__ oW,  const float* __restrict__ ob,
                    float* __restrict__ out)
{
    const int tid  = blockIdx.x * blockDim.x + threadIdx.x;
    const int pr   = tid >> 4;          // batch pair
    const int u    = tid & 15;          // hidden unit
    const int slot = threadIdx.x >> 4;  // half-warp slot (0..7)

    // per-slot 112 floats; slot stride mod 32 banks = 16 -> no cross-half-warp
    // bank collisions. buf0 e0 @0B, e1 @96B; buf1 e0 @192B, e1 @288B.
    __shared__ __align__(16) float sm[8][112];
    const unsigned sb = (unsigned)__cvta_generic_to_shared(&sm[slot][0]);

    // ---------------- encoder weights ----------------
    u64 wh[4][8]; u64 wi[4][4]; float bias[4];
    #pragma unroll
    for (int g = 0; g < 4; ++g) {
        const int r = g * H_ + u;
        bias[g] = ebih[r] + ebhh[r];
        #pragma unroll
        for (int j = 0; j < 8; ++j)
            wh[g][j] = pk2(eWhh[r * H_ + 2 * j], eWhh[r * H_ + 2 * j + 1]);
        #pragma unroll
        for (int j = 0; j < 4; ++j)
            wi[g][j] = pk2(eWih[r * F_ + 2 * j], eWih[r * F_ + 2 * j + 1]);
    }

    float h0 = 0.f, c0 = 0.f, h1 = 0.f, c1 = 0.f;
    sm[slot][u] = 0.f;  sm[slot][24 + u] = 0.f;
    CBAR();

    const float* xr = x + (size_t)(2 * pr) * XOFF;
    prefetch_l1(xr + XOFF);

    // prologue: input projection for t=0
    u64 xp[8], nx[8];
    {
        u64 xv[4], yv[4];
        ldg2(xv[0], xv[1], xr);         ldg2(xv[2], xv[3], xr + 4);
        ldg2(yv[0], yv[1], xr + XOFF);  ldg2(yv[2], yv[3], xr + XOFF + 4);
        #pragma unroll
        for (int g = 0; g < 4; ++g) {
            xp[g] = pk2(bias[g], 0.f);  xp[4 + g] = pk2(bias[g], 0.f);
        }
        #pragma unroll
        for (int j = 0; j < 4; ++j)
            #pragma unroll
            for (int g = 0; g < 4; ++g) {
                fma2(xp[g],     xv[j], wi[g][j]);
                fma2(xp[4 + g], yv[j], wi[g][j]);
            }
    }

    // ---------------- encoder recurrence (ping-pong xp/nx) ----------------
    for (int t = 0; t < T_; t += 2) {
        estep(t,     sb + 0,   sb + 192, xr, xp, nx, wh, wi, bias, h0, c0, h1, c1, u, true);
        estep(t + 1, sb + 192, sb + 0,   xr, nx, xp, wh, wi, bias, h0, c0, h1, c1, u, false);
    }
    CBAR();
    // hT of both elements in buf0 (word offsets 0 / 24)

    // ---------------- decoder setup ----------------
    u64 xg[8];
    #pragma unroll
    for (int g = 0; g < 4; ++g) {
        const int r = g * H_ + u;
        float a = dbih[r] + dbhh[r], bb = a;
        #pragma unroll
        for (int k = 0; k < H_; ++k) {
            float w = __ldg(&dWih[r * H_ + k]);
            a  += sm[slot][k]      * w;
            bb += sm[slot][24 + k] * w;
        }
        xg[g]     = pk2(a, 0.f);
        xg[4 + g] = pk2(bb, 0.f);
        #pragma unroll
        for (int j = 0; j < 8; ++j)
            wh[g][j] = pk2(dWhh[r * H_ + 2 * j], dWhh[r * H_ + 2 * j + 1]);  // reuse
    }
    u64 ow[8];
    const int fo = u & 7;
    #pragma unroll
    for (int j = 0; j < 8; ++j)
        ow[j] = pk2(oW[fo * H_ + 2 * j], oW[fo * H_ + 2 * j + 1]);
    const float obv = __ldg(&ob[fo]);

    CBAR();
    sm[slot][u] = 0.f;  sm[slot][24 + u] = 0.f;   // decoder h0 = 0
    h0 = c0 = h1 = c1 = 0.f;
    CBAR();

    float* outp0 = out + (size_t)(2 * pr) * XOFF;
    float* outp1 = outp0 + XOFF;

    // ---------------- decoder recurrence + fused output head ----------------
    for (int t = 0; t < T_; t += 2) {
        dstep(t,     sb + 0,   sb + 192, xg, wh, ow, obv, h0, c0, h1, c1, outp0, outp1, u);
        dstep(t + 1, sb + 192, sb + 0,   xg, wh, ow, obv, h0, c0, h1, c1, outp0, outp1, u);
    }
    CBAR();

    // epilogue: project decoded[T-1] (final h in buf0)
    {
        u64 p[8], q[8];
        lds2(p[0],p[1], sb);       lds2(p[2],p[3], sb + 16);
        lds2(p[4],p[5], sb + 32);  lds2(p[6],p[7], sb + 48);
        lds2(q[0],q[1], sb + 96);  lds2(q[2],q[3], sb + 112);
        lds2(q[4],q[5], sb + 128); lds2(q[6],q[7], sb + 144);
        u64 oa, oc;
        mul2(oa, p[0], ow[0]);  mul2(oc, q[0], ow[0]);
        #pragma unroll
        for (int j = 1; j < 8; ++j) {
            fma2(oa, p[j], ow[j]);
            fma2(oc, q[j], ow[j]);
        }
        if (u < 8) {
            outp0[(T_ - 1) * F_ + u] = hadd2(oa) + obv;
            outp1[(T_ - 1) * F_ + u] = hadd2(oc) + obv;
        }
    }
}

extern "C" void kernel_launch(void* const* d_in, const int* in_sizes, int n_in,
                              void* d_out, int out_size)
{
    const float* x    = (const float*)d_in[0];
    const float* eWih = (const float*)d_in[1];
    const float* eWhh = (const float*)d_in[2];
    const float* ebih = (const float*)d_in[3];
    const float* ebhh = (const float*)d_in[4];
    const float* dWih = (const float*)d_in[5];
    const float* dWhh = (const float*)d_in[6];
    const float* dbih = (const float*)d_in[7];
    const float* dbhh = (const float*)d_in[8];
    const float* oW   = (const float*)d_in[9];
    const float* ob   = (const float*)d_in[10];
    float* out = (float*)d_out;

    // 2048 batch pairs * 16 lanes = 32768 threads; 128/block -> 256 blocks
    lstm_ae_kernel<<<256, 128>>>(x, eWih, eWhh, ebih, ebhh,
                                 dWih, dWhh, dbih, dbhh, oW, ob, out);
}

// round 11
// speedup vs baseline: 1.0620x; 1.0620x over previous
#include <cuda_runtime.h>

// LSTM autoencoder, fully fused. B=4096, T=512, F=8, H=16.
// R6: return to the R1 shuffle skeleton (the only config that achieved 70%
// issue) + all instruction-count wins that don't touch shared memory:
//  - paired shfl -> f32x2 FFMA for whh / wih / output head
//  - tanh.approx acts, 0.5 sigmoid scale folded into weights/biases at setup
//  - zero smem, zero volatile ops in the recurrence loops
// Half-warp (16 lanes) per batch element; lane = hidden unit.

#define B_ 4096
#define T_ 512
#define F_ 8
#define H_ 16

typedef unsigned long long u64;

__device__ __forceinline__ u64 pk2(float lo, float hi) {
    u64 r; asm("mov.b64 %0,{%1,%2};" : "=l"(r) : "f"(lo), "f"(hi)); return r;
}
__device__ __forceinline__ void fma2(u64& d, u64 a, u64 b) {
    asm("fma.rn.f32x2 %0,%1,%2,%0;" : "+l"(d) : "l"(a), "l"(b));
}
__device__ __forceinline__ float hadd2(u64 v) {
    float lo, hi; asm("mov.b64 {%0,%1},%2;" : "=f"(lo), "=f"(hi) : "l"(v));
    return lo + hi;
}
__device__ __forceinline__ float tanh_fast(float x) {
    float r; asm("tanh.approx.f32 %0,%1;" : "=f"(r) : "f"(x)); return r;
}

__global__ __launch_bounds__(128, 4)
void lstm_ae_kernel(const float* __restrict__ x,
                    const float* __restrict__ eWih, const float* __restrict__ eWhh,
                    const float* __restrict__ ebih, const float* __restrict__ ebhh,
                    const float* __restrict__ dWih, const float* __restrict__ dWhh,
                    const float* __restrict__ dbih, const float* __restrict__ dbhh,
                    const float* __restrict__ oW,  const float* __restrict__ ob,
                    float* __restrict__ out)
{
    const int tid = blockIdx.x * blockDim.x + threadIdx.x;
    const int b   = tid >> 4;     // batch element (half-warp)
    const int u   = tid & 15;     // hidden unit for this lane
    const unsigned FULL = 0xffffffffu;

    // ----- encoder weights, register resident, packed in k-pairs.
    // Sigmoid gates (i=0, f=1, o=3) pre-scaled by 0.5 so
    // sigmoid(z) = 0.5*tanh(0.5 z) + 0.5 needs no per-step FMUL.
    u64 wh[4][8];   // hidden->gate rows
    u64 wi[4][4];   // input->gate rows
    float bias[4];
    #pragma unroll
    for (int g = 0; g < 4; ++g) {
        const int r = g * H_ + u;
        const float s = (g == 2) ? 1.0f : 0.5f;
        bias[g] = s * (ebih[r] + ebhh[r]);
        #pragma unroll
        for (int j = 0; j < 8; ++j)
            wh[g][j] = pk2(s * eWhh[r * H_ + 2 * j], s * eWhh[r * H_ + 2 * j + 1]);
        #pragma unroll
        for (int j = 0; j < 4; ++j)
            wi[g][j] = pk2(s * eWih[r * F_ + 2 * j], s * eWih[r * F_ + 2 * j + 1]);
    }

    // ---------------- encoder recurrence ----------------
    float h = 0.0f, c = 0.0f;
    const float4* xp4 = reinterpret_cast<const float4*>(x + (size_t)b * T_ * F_);
    float4 xa = __ldg(xp4 + 0);
    float4 xb = __ldg(xp4 + 1);

    for (int t = 0; t < T_; ++t) {
        float4 na, nb;
        if (t + 1 < T_) {                    // prefetch next step's x
            na = __ldg(xp4 + 2 * (t + 1));
            nb = __ldg(xp4 + 2 * (t + 1) + 1);
        }
        u64 a0 = pk2(bias[0], 0.f), a1 = pk2(bias[1], 0.f);
        u64 a2 = pk2(bias[2], 0.f), a3 = pk2(bias[3], 0.f);

        // input projection (float4 components are adjacent regs -> pk2 free)
        u64 q;
        q = pk2(xa.x, xa.y); fma2(a0,q,wi[0][0]); fma2(a1,q,wi[1][0]); fma2(a2,q,wi[2][0]); fma2(a3,q,wi[3][0]);
        q = pk2(xa.z, xa.w); fma2(a0,q,wi[0][1]); fma2(a1,q,wi[1][1]); fma2(a2,q,wi[2][1]); fma2(a3,q,wi[3][1]);
        q = pk2(xb.x, xb.y); fma2(a0,q,wi[0][2]); fma2(a1,q,wi[1][2]); fma2(a2,q,wi[2][2]); fma2(a3,q,wi[3][2]);
        q = pk2(xb.z, xb.w); fma2(a0,q,wi[0][3]); fma2(a1,q,wi[1][3]); fma2(a2,q,wi[2][3]); fma2(a3,q,wi[3][3]);

        // recurrent projection: paired shfl broadcast + packed FFMA
        #pragma unroll
        for (int k = 0; k < 8; ++k) {
            float hl = __shfl_sync(FULL, h, 2 * k,     16);
            float hh = __shfl_sync(FULL, h, 2 * k + 1, 16);
            u64 hp = pk2(hl, hh);
            fma2(a0, hp, wh[0][k]);
            fma2(a1, hp, wh[1][k]);
            fma2(a2, hp, wh[2][k]);
            fma2(a3, hp, wh[3][k]);
        }

        float ig = __fmaf_rn(0.5f, tanh_fast(hadd2(a0)), 0.5f);
        float fg = __fmaf_rn(0.5f, tanh_fast(hadd2(a1)), 0.5f);
        float gg = tanh_fast(hadd2(a2));
        float og = __fmaf_rn(0.5f, tanh_fast(hadd2(a3)), 0.5f);
        c = __fmaf_rn(fg, c, ig * gg);
        h = og * tanh_fast(c);

        xa = na; xb = nb;
    }

    // ---------------- decoder setup ----------------
    // Input is hT repeated -> input projection is a per-batch constant.
    float xpg[4];
    #pragma unroll
    for (int g = 0; g < 4; ++g) {
        const int r = g * H_ + u;
        float a = dbih[r] + dbhh[r];
        #pragma unroll
        for (int k = 0; k < H_; ++k) {
            float hk = __shfl_sync(FULL, h, k, 16);
            a += hk * __ldg(&dWih[r * H_ + k]);
        }
        if (g != 2) a *= 0.5f;          // fold sigmoid scale
        xpg[g] = a;
        const float s = (g == 2) ? 1.0f : 0.5f;
        #pragma unroll
        for (int j = 0; j < 8; ++j)
            wh[g][j] = pk2(s * dWhh[r * H_ + 2 * j], s * dWhh[r * H_ + 2 * j + 1]);
    }
    // output head: lane computes feature (u&7); lanes 0-7 store
    u64 ow[8];
    const int fo = u & 7;
    #pragma unroll
    for (int j = 0; j < 8; ++j)
        ow[j] = pk2(oW[fo * H_ + 2 * j], oW[fo * H_ + 2 * j + 1]);
    const float obv = __ldg(&ob[fo]);

    // ---------------- decoder recurrence + fused output head ----------------
    h = 0.0f; c = 0.0f;
    float* outp = out + (size_t)b * T_ * F_;

    for (int t = 0; t < T_; ++t) {
        u64 a0 = pk2(xpg[0], 0.f), a1 = pk2(xpg[1], 0.f);
        u64 a2 = pk2(xpg[2], 0.f), a3 = pk2(xpg[3], 0.f);
        u64 oa = pk2(obv, 0.f);

        #pragma unroll
        for (int k = 0; k < 8; ++k) {
            float hl = __shfl_sync(FULL, h, 2 * k,     16);   // h_{t-1}
            float hh = __shfl_sync(FULL, h, 2 * k + 1, 16);
            u64 hp = pk2(hl, hh);
            fma2(a0, hp, wh[0][k]);
            fma2(a1, hp, wh[1][k]);
            fma2(a2, hp, wh[2][k]);
            fma2(a3, hp, wh[3][k]);
            fma2(oa, hp, ow[k]);                              // head on h_{t-1}
        }
        if (t > 0 && u < 8) outp[(t - 1) * F_ + u] = hadd2(oa);

        float ig = __fmaf_rn(0.5f, tanh_fast(hadd2(a0)), 0.5f);
        float fg = __fmaf_rn(0.5f, tanh_fast(hadd2(a1)), 0.5f);
        float gg = tanh_fast(hadd2(a2));
        float og = __fmaf_rn(0.5f, tanh_fast(hadd2(a3)), 0.5f);
        c = __fmaf_rn(fg, c, ig * gg);
        h = og * tanh_fast(c);
    }

    // epilogue: project decoded[T-1] (final h)
    {
        u64 oa = pk2(obv, 0.f);
        #pragma unroll
        for (int k = 0; k < 8; ++k) {
            float hl = __shfl_sync(FULL, h, 2 * k,     16);
            float hh = __shfl_sync(FULL, h, 2 * k + 1, 16);
            u64 hp = pk2(hl, hh);
            fma2(oa, hp, ow[k]);
        }
        if (u < 8) outp[(T_ - 1) * F_ + u] = hadd2(oa);
    }
}

extern "C" void kernel_launch(void* const* d_in, const int* in_sizes, int n_in,
                              void* d_out, int out_size)
{
    const float* x    = (const float*)d_in[0];
    const float* eWih = (const float*)d_in[1];
    const float* eWhh = (const float*)d_in[2];
    const float* ebih = (const float*)d_in[3];
    const float* ebhh = (const float*)d_in[4];
    const float* dWih = (const float*)d_in[5];
    const float* dWhh = (const float*)d_in[6];
    const float* dbih = (const float*)d_in[7];
    const float* dbhh = (const float*)d_in[8];
    const float* oW   = (const float*)d_in[9];
    const float* ob   = (const float*)d_in[10];
    float* out = (float*)d_out;

    // 4096 elements * 16 lanes = 65536 threads; 128/block -> 512 blocks
    lstm_ae_kernel<<<512, 128>>>(x, eWih, eWhh, ebih, ebhh,
                                 dWih, dWhh, dbih, dbhh, oW, ob, out);
}